// round 13
// baseline (speedup 1.0000x reference)
#include <cuda_runtime.h>
#include <cuda_bf16.h>

#define NBX 2048
#define NBY 2048
#define HEIGHT 4096
#define BIN_AREA 4.0f

// Each thread computes 4 bins along j (y-bin axis).
// Bin (i,j) aggregates site types at (2i,2j),(2i,2j+1),(2i+1,2j),(2i+1,2j+1).
// Per-site area replicates reference fp32 rounding: wx = rn(xf+nw)-xf, wy = rn(yf+nh)-yf.
//
// CONVERGED (R2..R12 sweep): 256 thr/block, 4 bins/thread, plain __ldg int4
// loads, __stcs float4 stores, natural regalloc (40 regs, 6 blocks/SM).
// Runs ~1.5% above the compulsory-traffic floor: ~127MB DRAM/replay
// (64MB input read + ~63MB output writeback after cross-replay L2 merge)
// at ~5 TB/s mixed-stream HBM bandwidth. All cache-policy hints, occupancy,
// width, and grid-shape perturbations measured neutral or worse.
__global__ __launch_bounds__(256) void demand_map_kernel(
    const int* __restrict__ st,
    const float* __restrict__ nsx,
    const float* __restrict__ nsy,
    float* __restrict__ out)
{
    int tid = blockIdx.x * blockDim.x + threadIdx.x;   // 2048 * 512 threads
    int i  = tid >> 9;          // x-bin row
    int jq = tid & 511;         // group of 4 y-bins
    int ybase = jq << 3;        // 8 site columns per thread
    int x0 = i << 1;
    int x1 = x0 + 1;

    // per-type node sizes (types 1..3 -> slots 0..2)
    float nwx0 = __ldg(&nsx[1]), nwx1 = __ldg(&nsx[2]), nwx2 = __ldg(&nsx[3]);
    float nwy0 = __ldg(&nsy[1]), nwy1 = __ldg(&nsy[2]), nwy2 = __ldg(&nsy[3]);

    float xf0 = (float)x0, xf1 = (float)x1;
    // wx per (row, slot) — exact fp32 replication of reference
    float wxA[3], wxB[3];
    wxA[0] = __fsub_rn(__fadd_rn(xf0, nwx0), xf0);
    wxA[1] = __fsub_rn(__fadd_rn(xf0, nwx1), xf0);
    wxA[2] = __fsub_rn(__fadd_rn(xf0, nwx2), xf0);
    wxB[0] = __fsub_rn(__fadd_rn(xf1, nwx0), xf1);
    wxB[1] = __fsub_rn(__fadd_rn(xf1, nwx1), xf1);
    wxB[2] = __fsub_rn(__fadd_rn(xf1, nwx2), xf1);

    const int4* r0 = (const int4*)(st + (size_t)x0 * HEIGHT + ybase);
    const int4* r1 = (const int4*)(st + (size_t)x1 * HEIGHT + ybase);
    int4 a0 = __ldg(&r0[0]);
    int4 a1 = __ldg(&r0[1]);
    int4 b0 = __ldg(&r1[0]);
    int4 b1 = __ldg(&r1[1]);

    int ta[8] = {a0.x, a0.y, a0.z, a0.w, a1.x, a1.y, a1.z, a1.w};
    int tb[8] = {b0.x, b0.y, b0.z, b0.w, b1.x, b1.y, b1.z, b1.w};

    float o0[4], o5[4], o6[4];

    #pragma unroll
    for (int b = 0; b < 4; b++) {
        float c0 = 0.0f, c1 = 0.0f, c2 = 0.0f;
        #pragma unroll
        for (int s = 0; s < 2; s++) {
            int ys = ybase + (b << 1) + s;
            float yf = (float)ys;
            // wy per slot for this site column (shared by both site rows)
            float wy0 = __fsub_rn(__fadd_rn(yf, nwy0), yf);
            float wy1 = __fsub_rn(__fadd_rn(yf, nwy1), yf);
            float wy2 = __fsub_rn(__fadd_rn(yf, nwy2), yf);
            int t0 = ta[(b << 1) + s];
            int t1 = tb[(b << 1) + s];
            // branchless predicated accumulation (types are random -> avoid divergence)
            c0 += (t0 == 1) ? __fmul_rn(wxA[0], wy0) : 0.0f;
            c1 += (t0 == 2) ? __fmul_rn(wxA[1], wy1) : 0.0f;
            c2 += (t0 == 3) ? __fmul_rn(wxA[2], wy2) : 0.0f;
            c0 += (t1 == 1) ? __fmul_rn(wxB[0], wy0) : 0.0f;
            c1 += (t1 == 2) ? __fmul_rn(wxB[1], wy1) : 0.0f;
            c2 += (t1 == 3) ? __fmul_rn(wxB[2], wy2) : 0.0f;
        }
        o0[b] = BIN_AREA - c0;
        o5[b] = BIN_AREA - c1;
        o6[b] = BIN_AREA - c2;
    }

    float4 v0 = make_float4(o0[0], o0[1], o0[2], o0[3]);
    float4 v5 = make_float4(o5[0], o5[1], o5[2], o5[3]);
    float4 v6 = make_float4(o6[0], o6[1], o6[2], o6[3]);

    float4* o = (float4*)out;
    size_t plane4 = (size_t)NBX * NBY / 4;      // 1,048,576 float4 per plane
    size_t p = (size_t)i * 512 + jq;            // float4 index within plane

    // streaming stores: evict-first; fire-and-forget
    __stcs(&o[0 * plane4 + p], v0);
    __stcs(&o[1 * plane4 + p], v0);
    __stcs(&o[2 * plane4 + p], v0);
    __stcs(&o[3 * plane4 + p], v0);
    __stcs(&o[4 * plane4 + p], v0);
    __stcs(&o[5 * plane4 + p], v5);
    __stcs(&o[6 * plane4 + p], v6);
}

extern "C" void kernel_launch(void* const* d_in, const int* in_sizes, int n_in,
                              void* d_out, int out_size) {
    const int*   st  = (const int*)d_in[0];     // site_type_map [4096*4096] int32
    const float* nsx = (const float*)d_in[1];   // node_size_x [4]
    const float* nsy = (const float*)d_in[2];   // node_size_y [4]
    float* out = (float*)d_out;                 // [7, 2048, 2048] float32

    // 2048 bin-rows * 512 threads/row (4 bins each) = 1,048,576 threads
    dim3 block(256);
    dim3 grid((2048u * 512u) / 256u);
    demand_map_kernel<<<grid, block>>>(st, nsx, nsy, out);
}

// round 15
// speedup vs baseline: 1.0356x; 1.0356x over previous
#include <cuda_runtime.h>
#include <cuda_bf16.h>
#include <cstdint>

#define NBX 2048
#define NBY 2048
#define HEIGHT 4096
#define BIN_AREA 4.0f

// Each thread computes 4 bins along j. Bin (i,j) aggregates site types at
// (2i,2j),(2i,2j+1),(2i+1,2j),(2i+1,2j+1). Per-site area replicates reference
// fp32 rounding: wx = rn(xf+nw)-xf, wy = rn(yf+nh)-yf.
//
// Store-side bulk batching: each CTA's output is 4KB contiguous per plane;
// stage in SMEM and issue one 4KB cp.async.bulk (shared->global) per plane
// -> 7 large sequential write bursts per CTA instead of 7x256 scattered 16B
// stores. Targets HBM write-burst efficiency / read-write turnaround.
__global__ __launch_bounds__(256) void demand_map_kernel(
    const int* __restrict__ st,
    const float* __restrict__ nsx,
    const float* __restrict__ nsy,
    float* __restrict__ out)
{
    __shared__ __align__(128) float sm[7][1024];   // 28KB: per-plane 4KB staging

    int tid = blockIdx.x * blockDim.x + threadIdx.x;   // 2048 * 512 threads
    int i  = tid >> 9;          // x-bin row
    int jq = tid & 511;         // group of 4 y-bins
    int ybase = jq << 3;        // 8 site columns per thread
    int x0 = i << 1;
    int x1 = x0 + 1;

    // per-type node sizes (types 1..3 -> slots 0..2)
    float nwx0 = __ldg(&nsx[1]), nwx1 = __ldg(&nsx[2]), nwx2 = __ldg(&nsx[3]);
    float nwy0 = __ldg(&nsy[1]), nwy1 = __ldg(&nsy[2]), nwy2 = __ldg(&nsy[3]);

    float xf0 = (float)x0, xf1 = (float)x1;
    // wx per (row, slot) — exact fp32 replication of reference
    float wxA[3], wxB[3];
    wxA[0] = __fsub_rn(__fadd_rn(xf0, nwx0), xf0);
    wxA[1] = __fsub_rn(__fadd_rn(xf0, nwx1), xf0);
    wxA[2] = __fsub_rn(__fadd_rn(xf0, nwx2), xf0);
    wxB[0] = __fsub_rn(__fadd_rn(xf1, nwx0), xf1);
    wxB[1] = __fsub_rn(__fadd_rn(xf1, nwx1), xf1);
    wxB[2] = __fsub_rn(__fadd_rn(xf1, nwx2), xf1);

    const int4* r0 = (const int4*)(st + (size_t)x0 * HEIGHT + ybase);
    const int4* r1 = (const int4*)(st + (size_t)x1 * HEIGHT + ybase);
    int4 a0 = __ldg(&r0[0]);
    int4 a1 = __ldg(&r0[1]);
    int4 b0 = __ldg(&r1[0]);
    int4 b1 = __ldg(&r1[1]);

    int ta[8] = {a0.x, a0.y, a0.z, a0.w, a1.x, a1.y, a1.z, a1.w};
    int tb[8] = {b0.x, b0.y, b0.z, b0.w, b1.x, b1.y, b1.z, b1.w};

    float o0[4], o5[4], o6[4];

    #pragma unroll
    for (int b = 0; b < 4; b++) {
        float c0 = 0.0f, c1 = 0.0f, c2 = 0.0f;
        #pragma unroll
        for (int s = 0; s < 2; s++) {
            int ys = ybase + (b << 1) + s;
            float yf = (float)ys;
            float wy0 = __fsub_rn(__fadd_rn(yf, nwy0), yf);
            float wy1 = __fsub_rn(__fadd_rn(yf, nwy1), yf);
            float wy2 = __fsub_rn(__fadd_rn(yf, nwy2), yf);
            int t0 = ta[(b << 1) + s];
            int t1 = tb[(b << 1) + s];
            c0 += (t0 == 1) ? __fmul_rn(wxA[0], wy0) : 0.0f;
            c1 += (t0 == 2) ? __fmul_rn(wxA[1], wy1) : 0.0f;
            c2 += (t0 == 3) ? __fmul_rn(wxA[2], wy2) : 0.0f;
            c0 += (t1 == 1) ? __fmul_rn(wxB[0], wy0) : 0.0f;
            c1 += (t1 == 2) ? __fmul_rn(wxB[1], wy1) : 0.0f;
            c2 += (t1 == 3) ? __fmul_rn(wxB[2], wy2) : 0.0f;
        }
        o0[b] = BIN_AREA - c0;
        o5[b] = BIN_AREA - c1;
        o6[b] = BIN_AREA - c2;
    }

    // stage to SMEM (16B per thread per plane; conflict-free)
    int tx4 = threadIdx.x << 2;
    float4 v0 = make_float4(o0[0], o0[1], o0[2], o0[3]);
    float4 v5 = make_float4(o5[0], o5[1], o5[2], o5[3]);
    float4 v6 = make_float4(o6[0], o6[1], o6[2], o6[3]);
    *(float4*)&sm[0][tx4] = v0;
    *(float4*)&sm[1][tx4] = v0;
    *(float4*)&sm[2][tx4] = v0;
    *(float4*)&sm[3][tx4] = v0;
    *(float4*)&sm[4][tx4] = v0;
    *(float4*)&sm[5][tx4] = v5;
    *(float4*)&sm[6][tx4] = v6;

    __syncthreads();
    asm volatile("fence.proxy.async.shared::cta;" ::: "memory");

    // one 4KB bulk store per plane, issued by one thread
    if (threadIdx.x == 0) {
        size_t plane = (size_t)NBX * NBY;               // floats per plane
        size_t blk_off = (size_t)blockIdx.x * 1024;     // this CTA's 1024 floats
        #pragma unroll
        for (int pl = 0; pl < 7; pl++) {
            float* dst = out + pl * plane + blk_off;
            unsigned int saddr;
            asm("{ .reg .u64 t; cvta.to.shared.u64 t, %1; cvt.u32.u64 %0, t; }"
                : "=r"(saddr) : "l"(&sm[pl][0]));
            asm volatile("cp.async.bulk.global.shared::cta.bulk_group [%0], [%1], %2;"
                         :: "l"(dst), "r"(saddr), "n"(4096) : "memory");
        }
        asm volatile("cp.async.bulk.commit_group;" ::: "memory");
        asm volatile("cp.async.bulk.wait_group 0;" ::: "memory");
    }
}

extern "C" void kernel_launch(void* const* d_in, const int* in_sizes, int n_in,
                              void* d_out, int out_size) {
    const int*   st  = (const int*)d_in[0];     // site_type_map [4096*4096] int32
    const float* nsx = (const float*)d_in[1];   // node_size_x [4]
    const float* nsy = (const float*)d_in[2];   // node_size_y [4]
    float* out = (float*)d_out;                 // [7, 2048, 2048] float32

    // 2048 bin-rows * 512 threads/row (4 bins each) = 1,048,576 threads
    dim3 block(256);
    dim3 grid((2048u * 512u) / 256u);
    demand_map_kernel<<<grid, block>>>(st, nsx, nsy, out);
}